// round 16
// baseline (speedup 1.0000x reference)
#include <cuda_runtime.h>
#include <cstdint>

#define B_ 4
#define S_ 4096
#define E_ 256
#define H_ 64

typedef unsigned long long ull;

// -------- scratch (device globals: allocation-free) --------
__device__ float g_q [B_ * S_ * H_];   // row-major, scaled by log2(e)/16, tf32-rounded
__device__ float g_k [B_ * S_ * H_];   // row-major, tf32-rounded
__device__ float g_vT[B_ * S_ * H_];   // per-64-row-block transposed [blk][h][64 kc], tf32-rounded

// -------- packed f32x2 helpers (projection) --------
__device__ __forceinline__ ull fma2(ull a, ull b, ull c) {
    ull d; asm("fma.rn.f32x2 %0, %1, %2, %3;" : "=l"(d) : "l"(a), "l"(b), "l"(c)); return d;
}
__device__ __forceinline__ ull dup2(float x) {
    ull d; asm("mov.b64 %0, {%1, %1};" : "=l"(d) : "f"(x)); return d;
}
__device__ __forceinline__ void unpack2(ull v, float& x, float& y) {
    asm("mov.b64 {%0, %1}, %2;" : "=f"(x), "=f"(y) : "l"(v));
}
__device__ __forceinline__ float exp2_fast(float x) {
    float r; asm("ex2.approx.ftz.f32 %0, %1;" : "=f"(r) : "f"(x)); return r;
}
__device__ __forceinline__ float tf32r(float x) {
    float r; asm("cvt.rna.tf32.f32 %0, %1;" : "=f"(r) : "f"(x)); return r;
}

// ============================================================
// Projection (FFMA2): out = emb @ W for a 64-row tile.
// y==0: Q row-major (scaled), y==1: K row-major, y==2: V transposed per block.
// ============================================================
#define ET_STRIDE 68
#define PROJ_SMEM ((E_ * ET_STRIDE + E_ * H_) * 4)

__global__ __launch_bounds__(256, 1) void proj_kernel(
    const float* __restrict__ emb,
    const float* __restrict__ wq,
    const float* __restrict__ wk,
    const float* __restrict__ wv) {
    extern __shared__ float ps[];
    float* embT = ps;
    float* Ws   = ps + E_ * ET_STRIDE;

    const float* w; float* outp; float scale; int transposed;
    if (blockIdx.y == 0)      { w = wq; outp = g_q;  scale = 1.4426950408889634f * 0.0625f; transposed = 0; }
    else if (blockIdx.y == 1) { w = wk; outp = g_k;  scale = 1.0f; transposed = 0; }
    else                      { w = wv; outp = g_vT; scale = 1.0f; transposed = 1; }

    const int tid = threadIdx.x;
    const int bx  = blockIdx.x;

    const float4* eg = reinterpret_cast<const float4*>(emb + (size_t)bx * 64 * E_);
    #pragma unroll
    for (int k = 0; k < 16; ++k) {
        int idx = tid + 256 * k;
        int row = idx >> 6;
        int e4  = idx & 63;
        float4 v = eg[idx];
        int E0 = e4 * 4;
        int base = E0 * ET_STRIDE + (row ^ (E0 & 60));
        embT[base]                 = v.x;
        embT[base + ET_STRIDE]     = v.y;
        embT[base + 2 * ET_STRIDE] = v.z;
        embT[base + 3 * ET_STRIDE] = v.w;
    }
    {
        const float4* wg = reinterpret_cast<const float4*>(w);
        float4* ws4 = reinterpret_cast<float4*>(Ws);
        #pragma unroll
        for (int k = 0; k < 16; ++k) ws4[tid + 256 * k] = wg[tid + 256 * k];
    }
    __syncthreads();

    const int ty = tid >> 4, tx = tid & 15;
    const int r0 = ty * 4, h0 = tx * 4;

    ull acc[4][2];
    #pragma unroll
    for (int i = 0; i < 4; ++i) { acc[i][0] = 0ULL; acc[i][1] = 0ULL; }

    #pragma unroll 4
    for (int e = 0; e < E_; ++e) {
        float4 a = *reinterpret_cast<const float4*>(&embT[e * ET_STRIDE + (r0 ^ (e & 60))]);
        ulonglong2 wv2 = *reinterpret_cast<const ulonglong2*>(&Ws[e * H_ + h0]);
        ull a0 = dup2(a.x), a1 = dup2(a.y), a2 = dup2(a.z), a3 = dup2(a.w);
        acc[0][0] = fma2(a0, wv2.x, acc[0][0]); acc[0][1] = fma2(a0, wv2.y, acc[0][1]);
        acc[1][0] = fma2(a1, wv2.x, acc[1][0]); acc[1][1] = fma2(a1, wv2.y, acc[1][1]);
        acc[2][0] = fma2(a2, wv2.x, acc[2][0]); acc[2][1] = fma2(a2, wv2.y, acc[2][1]);
        acc[3][0] = fma2(a3, wv2.x, acc[3][0]); acc[3][1] = fma2(a3, wv2.y, acc[3][1]);
    }

    float o[4][4];
    #pragma unroll
    for (int i = 0; i < 4; ++i) {
        unpack2(acc[i][0], o[i][0], o[i][1]);
        unpack2(acc[i][1], o[i][2], o[i][3]);
        #pragma unroll
        for (int c = 0; c < 4; ++c) o[i][c] = tf32r(o[i][c] * scale);
    }
    if (transposed) {
        #pragma unroll
        for (int c = 0; c < 4; ++c)
            *reinterpret_cast<float4*>(&outp[(size_t)bx * 4096 + (h0 + c) * 64 + r0]) =
                make_float4(o[0][c], o[1][c], o[2][c], o[3][c]);
    } else {
        #pragma unroll
        for (int i = 0; i < 4; ++i)
            *reinterpret_cast<float4*>(&outp[((size_t)bx * 64 + r0 + i) * H_ + h0]) =
                make_float4(o[i][0], o[i][1], o[i][2], o[i][3]);
    }
}

// ============================================================
// Warp-MMA tf32 flash attention, high-occupancy version.
// CTA: 64 q-rows, 256 threads (8 warps): rg=w>>1 (16 rows each),
// kg=w&1 (kv cols 32kg..+32). 16-row warps -> ~120 live regs,
// __launch_bounds__(256,2) pins 128 regs -> 16 warps/SM.
// ============================================================

__device__ __forceinline__ uint32_t smem_u32(const void* p) {
    uint32_t a;
    asm("{ .reg .u64 t; cvta.to.shared.u64 t, %1; cvt.u32.u64 %0, t; }" : "=r"(a) : "l"(p));
    return a;
}
__device__ __forceinline__ void mma_tf32(float& d0, float& d1, float& d2, float& d3,
                                         uint32_t a0, uint32_t a1, uint32_t a2, uint32_t a3,
                                         uint32_t b0, uint32_t b1) {
    asm volatile(
        "mma.sync.aligned.m16n8k8.row.col.f32.tf32.tf32.f32 "
        "{%0,%1,%2,%3}, {%4,%5,%6,%7}, {%8,%9}, {%0,%1,%2,%3};"
        : "+f"(d0), "+f"(d1), "+f"(d2), "+f"(d3)
        : "r"(a0), "r"(a1), "r"(a2), "r"(a3), "r"(b0), "r"(b1));
}
__device__ __forceinline__ void cp16(uint32_t dst, const void* src) {
    asm volatile("cp.async.ca.shared.global [%0], [%1], 16;" :: "r"(dst), "l"(src) : "memory");
}
__device__ __forceinline__ void cp_commit() {
    asm volatile("cp.async.commit_group;" ::: "memory");
}
__device__ __forceinline__ void cp_wait1() {
    asm volatile("cp.async.wait_group 1;" ::: "memory");
}
__device__ __forceinline__ void cp_wait0() {
    asm volatile("cp.async.wait_group 0;" ::: "memory");
}

#define KV_STRIDE 68
#define TILE_F (64 * KV_STRIDE)
#define OFF_K0 0
#define OFF_K1 TILE_F
#define OFF_V0 (2 * TILE_F)
#define OFF_V1 (3 * TILE_F)
#define FLASH_SMEM ((4 * TILE_F) * 4)           // 69632 bytes

#define OSH_STRIDE 66

// async-copy one 64x64 f32 tile into padded smem (256 threads)
__device__ __forceinline__ void cp_tile(uint32_t smf_byte, const float* src, int tid) {
    #pragma unroll
    for (int i = 0; i < 4; ++i) {
        int id = tid + 256 * i;          // 1024 16B chunks
        int r = id >> 4;
        int c16 = id & 15;
        cp16(smf_byte + (uint32_t)(r * KV_STRIDE + c16 * 4) * 4u,
             src + (size_t)r * 64 + c16 * 4);
    }
}

__global__ __launch_bounds__(256, 2) void flash_kernel(float* __restrict__ out) {
    extern __shared__ float fs[];
    const uint32_t smb = smem_u32(fs);
    const int tid = threadIdx.x;
    const int w = tid >> 5, lane = tid & 31;
    const int rg = w >> 1, kg = w & 1;
    const int gid = lane >> 2, tig = lane & 3;
    const int b = blockIdx.y, qblk = blockIdx.x;

    const float* kgb = g_k  + (size_t)b * S_ * H_;
    const float* vgb = g_vT + (size_t)(b * 64) * 4096;

    // preload K/V tile 0 first so the cp.async stream overlaps the Q LDGs
    cp_tile(smb + OFF_K0 * 4, kgb, tid);
    cp_tile(smb + OFF_V0 * 4, vgb, tid);
    cp_commit();

    // ---- Q A-fragments: warp covers rows [16rg, 16rg+16) ----
    uint32_t qa[8][4];
    {
        const float* q0 = g_q + ((size_t)b * S_ + (size_t)qblk * 64 + 16 * rg) * H_;
        #pragma unroll
        for (int j = 0; j < 8; ++j) {
            const float* qr = q0 + (size_t)gid * H_ + 8 * j + tig;
            qa[j][0] = __float_as_uint(qr[0]);
            qa[j][1] = __float_as_uint(qr[8 * H_]);
            qa[j][2] = __float_as_uint(qr[4]);
            qa[j][3] = __float_as_uint(qr[8 * H_ + 4]);
        }
    }

    float oacc[8][4];
    #pragma unroll
    for (int ht = 0; ht < 8; ++ht)
        #pragma unroll
        for (int q = 0; q < 4; ++q) oacc[ht][q] = 0.0f;
    float lsum[2] = { 0.0f, 0.0f };

    const int srcA = (lane & ~3) | (tig >> 1);
    const int srcB = srcA + 2;
    const bool oddt = (tig & 1);

    for (int kt = 0; kt < 64; ++kt) {
        const int cur = kt & 1;
        if (kt < 63) {
            const int nf = (cur ^ 1) ? OFF_K1 : OFF_K0;
            const int nv = (cur ^ 1) ? OFF_V1 : OFF_V0;
            cp_tile(smb + nf * 4, kgb + (size_t)(kt + 1) * 64 * H_, tid);
            cp_tile(smb + nv * 4, vgb + (size_t)(kt + 1) * 4096, tid);
            cp_commit();
            cp_wait1();
        } else {
            cp_wait0();
        }
        __syncthreads();

        const float* Ks = fs + (cur ? OFF_K1 : OFF_K0);
        const float* Vs = fs + (cur ? OFF_V1 : OFF_V0);

        // ---- S = Q K^T over this warp's 32 kv cols ----
        float p[4][4];
        #pragma unroll
        for (int nt = 0; nt < 4; ++nt)
            #pragma unroll
            for (int q = 0; q < 4; ++q) p[nt][q] = 0.0f;

        #pragma unroll
        for (int j = 0; j < 8; ++j) {
            #pragma unroll
            for (int nt = 0; nt < 4; ++nt) {
                const float* kr = Ks + (32 * kg + 8 * nt + gid) * KV_STRIDE + 8 * j + tig;
                uint32_t kb0 = __float_as_uint(kr[0]);
                uint32_t kb1 = __float_as_uint(kr[4]);
                mma_tf32(p[nt][0], p[nt][1], p[nt][2], p[nt][3],
                         qa[j][0], qa[j][1], qa[j][2], qa[j][3], kb0, kb1);
            }
        }

        // ---- P = 2^S (log2 domain), tf32-rounded in place; partial l ----
        #pragma unroll
        for (int nt = 0; nt < 4; ++nt) {
            float p0 = exp2_fast(p[nt][0]);
            float p1 = exp2_fast(p[nt][1]);
            float p2 = exp2_fast(p[nt][2]);
            float p3 = exp2_fast(p[nt][3]);
            lsum[0] += p0 + p1;
            lsum[1] += p2 + p3;
            p[nt][0] = tf32r(p0);
            p[nt][1] = tf32r(p1);
            p[nt][2] = tf32r(p2);
            p[nt][3] = tf32r(p3);
        }

        // ---- O += P V over this warp's 32 kc (A-frags via quad shuffle) ----
        #pragma unroll
        for (int kb = 0; kb < 4; ++kb) {
            float x0 = __shfl_sync(0xffffffffu, p[kb][0], srcA);
            float x1 = __shfl_sync(0xffffffffu, p[kb][1], srcA);
            float y0 = __shfl_sync(0xffffffffu, p[kb][2], srcA);
            float y1 = __shfl_sync(0xffffffffu, p[kb][3], srcA);
            float z0 = __shfl_sync(0xffffffffu, p[kb][0], srcB);
            float z1 = __shfl_sync(0xffffffffu, p[kb][1], srcB);
            float u0 = __shfl_sync(0xffffffffu, p[kb][2], srcB);
            float u1 = __shfl_sync(0xffffffffu, p[kb][3], srcB);
            uint32_t A0 = __float_as_uint(oddt ? x1 : x0);
            uint32_t A1 = __float_as_uint(oddt ? y1 : y0);
            uint32_t A2 = __float_as_uint(oddt ? z1 : z0);
            uint32_t A3 = __float_as_uint(oddt ? u1 : u0);
            #pragma unroll
            for (int ht = 0; ht < 8; ++ht) {
                const float* vr = Vs + (8 * ht + gid) * KV_STRIDE + 32 * kg + 8 * kb + tig;
                uint32_t vb0 = __float_as_uint(vr[0]);
                uint32_t vb1 = __float_as_uint(vr[4]);
                mma_tf32(oacc[ht][0], oacc[ht][1], oacc[ht][2], oacc[ht][3],
                         A0, A1, A2, A3, vb0, vb1);
            }
        }
        __syncthreads();
    }

    // ---- epilogue: quad-reduce l, combine kc-halves through smem ----
    #pragma unroll
    for (int r = 0; r < 2; ++r) {
        lsum[r] += __shfl_xor_sync(0xffffffffu, lsum[r], 1);
        lsum[r] += __shfl_xor_sync(0xffffffffu, lsum[r], 2);
    }

    float* Osh = fs + OFF_K0;             // [64][OSH_STRIDE]
    float* Lsh = fs + OFF_V0;             // [64]
    if (kg == 1) {
        int row0 = 16 * rg + gid;
        if (tig == 0) { Lsh[row0] = lsum[0]; Lsh[row0 + 8] = lsum[1]; }
        #pragma unroll
        for (int ht = 0; ht < 8; ++ht) {
            int c = 8 * ht + 2 * tig;
            *reinterpret_cast<float2*>(&Osh[row0 * OSH_STRIDE + c]) =
                make_float2(oacc[ht][0], oacc[ht][1]);
            *reinterpret_cast<float2*>(&Osh[(row0 + 8) * OSH_STRIDE + c]) =
                make_float2(oacc[ht][2], oacc[ht][3]);
        }
    }
    __syncthreads();
    if (kg == 0) {
        float* ob = out + ((size_t)b * S_ + (size_t)qblk * 64) * H_;
        int row0 = 16 * rg + gid;
        int row1 = row0 + 8;
        float inv0 = 1.0f / (lsum[0] + Lsh[row0]);
        float inv1 = 1.0f / (lsum[1] + Lsh[row1]);
        #pragma unroll
        for (int ht = 0; ht < 8; ++ht) {
            int c = 8 * ht + 2 * tig;
            float2 q0 = *reinterpret_cast<const float2*>(&Osh[row0 * OSH_STRIDE + c]);
            float2 q1 = *reinterpret_cast<const float2*>(&Osh[row1 * OSH_STRIDE + c]);
            *reinterpret_cast<float2*>(&ob[(size_t)row0 * H_ + c]) =
                make_float2((oacc[ht][0] + q0.x) * inv0,
                            (oacc[ht][1] + q0.y) * inv0);
            *reinterpret_cast<float2*>(&ob[(size_t)row1 * H_ + c]) =
                make_float2((oacc[ht][2] + q1.x) * inv1,
                            (oacc[ht][3] + q1.y) * inv1);
        }
    }
}

// ============================================================
// launch
// ============================================================
extern "C" void kernel_launch(void* const* d_in, const int* in_sizes, int n_in,
                              void* d_out, int out_size) {
    const float* emb = (const float*)d_in[0];
    const float* wk  = (const float*)d_in[1];
    const float* wq  = (const float*)d_in[2];
    const float* wv  = (const float*)d_in[3];
    float* out = (float*)d_out;

    cudaFuncSetAttribute(proj_kernel,  cudaFuncAttributeMaxDynamicSharedMemorySize, PROJ_SMEM);
    cudaFuncSetAttribute(flash_kernel, cudaFuncAttributeMaxDynamicSharedMemorySize, FLASH_SMEM);

    dim3 pgrid(B_ * S_ / 64, 3);
    proj_kernel<<<pgrid, 256, PROJ_SMEM>>>(emb, wq, wk, wv);

    dim3 fgrid(S_ / 64, B_);
    flash_kernel<<<fgrid, 256, FLASH_SMEM>>>(out);
}

// round 17
// speedup vs baseline: 1.3632x; 1.3632x over previous
#include <cuda_runtime.h>
#include <cstdint>

#define B_ 4
#define S_ 4096
#define E_ 256
#define H_ 64

// -------- scratch (device globals: allocation-free) --------
__device__ float g_q[B_ * S_ * H_];   // row-major, scaled by log2(e)/16, tf32-rounded
__device__ float g_k[B_ * S_ * H_];   // row-major, tf32-rounded
__device__ float g_v[B_ * S_ * H_];   // row-major, tf32-rounded

__device__ __forceinline__ float exp2_fast(float x) {
    float r; asm("ex2.approx.ftz.f32 %0, %1;" : "=f"(r) : "f"(x)); return r;
}
__device__ __forceinline__ float tf32r(float x) {
    float r; asm("cvt.rna.tf32.f32 %0, %1;" : "=f"(r) : "f"(x)); return r;
}
__device__ __forceinline__ uint32_t smem_u32(const void* p) {
    uint32_t a;
    asm("{ .reg .u64 t; cvta.to.shared.u64 t, %1; cvt.u32.u64 %0, t; }" : "=r"(a) : "l"(p));
    return a;
}
__device__ __forceinline__ void mma_tf32(float& d0, float& d1, float& d2, float& d3,
                                         uint32_t a0, uint32_t a1, uint32_t a2, uint32_t a3,
                                         uint32_t b0, uint32_t b1) {
    asm volatile(
        "mma.sync.aligned.m16n8k8.row.col.f32.tf32.tf32.f32 "
        "{%0,%1,%2,%3}, {%4,%5,%6,%7}, {%8,%9}, {%0,%1,%2,%3};"
        : "+f"(d0), "+f"(d1), "+f"(d2), "+f"(d3)
        : "r"(a0), "r"(a1), "r"(a2), "r"(a3), "r"(b0), "r"(b1));
}
__device__ __forceinline__ void cp16(uint32_t dst, const void* src) {
    asm volatile("cp.async.ca.shared.global [%0], [%1], 16;" :: "r"(dst), "l"(src) : "memory");
}
__device__ __forceinline__ void cp_commit() {
    asm volatile("cp.async.commit_group;" ::: "memory");
}
__device__ __forceinline__ void cp_wait1() {
    asm volatile("cp.async.wait_group 1;" ::: "memory");
}
__device__ __forceinline__ void cp_wait0() {
    asm volatile("cp.async.wait_group 0;" ::: "memory");
}

// ============================================================
// Projection via tf32 warp-MMA: out[r,h] = dot(emb[r,:], W[:,h]).
// grid = (128 row-tiles of 128, 3 matrices), 256 threads (8 warps x 16 rows).
// emb/W staged with cp.async, tf32-rounded IN SMEM (one pass), then mma.
// ============================================================
#define EMB_STRIDE 260      // floats; 260 % 32 == 4 -> conflict-free A-frags
#define W_STRIDE   72       // floats; 72 % 32 == 8  -> conflict-free B-frags
#define PROJ_SMEM ((128 * EMB_STRIDE + 256 * W_STRIDE) * 4)   // 206,848 B

__global__ __launch_bounds__(256, 1) void proj_kernel(
    const float* __restrict__ emb,
    const float* __restrict__ wq,
    const float* __restrict__ wk,
    const float* __restrict__ wv) {
    extern __shared__ float ps[];
    float* embS = ps;                         // [128][EMB_STRIDE]
    float* WS   = ps + 128 * EMB_STRIDE;      // [256][W_STRIDE]
    const uint32_t smb = smem_u32(ps);

    const float* w; float* outp; float scale;
    if (blockIdx.y == 0)      { w = wq; outp = g_q; scale = 1.4426950408889634f * 0.0625f; }
    else if (blockIdx.y == 1) { w = wk; outp = g_k; scale = 1.0f; }
    else                      { w = wv; outp = g_v; scale = 1.0f; }

    const int tid = threadIdx.x;
    const int bx  = blockIdx.x;
    const float* eg = emb + (size_t)bx * 128 * E_;

    // ---- stage emb (128x256) and W (256x64) ----
    #pragma unroll
    for (int i = 0; i < 32; ++i) {
        int id = tid + 256 * i;              // 8192 chunks
        int r = id >> 6, c = id & 63;
        cp16(smb + (uint32_t)(r * EMB_STRIDE + c * 4) * 4u, eg + (size_t)r * E_ + c * 4);
    }
    #pragma unroll
    for (int i = 0; i < 16; ++i) {
        int id = tid + 256 * i;              // 4096 chunks
        int k = id >> 4, c = id & 15;
        cp16(smb + (uint32_t)(128 * EMB_STRIDE + k * W_STRIDE + c * 4) * 4u,
             w + (size_t)k * H_ + c * 4);
    }
    cp_commit();
    cp_wait0();
    __syncthreads();

    // ---- tf32-round in place (unbiased rna; avoids biased HW truncation) ----
    float4* e4 = reinterpret_cast<float4*>(embS);
    #pragma unroll
    for (int i = 0; i < 32; ++i) {
        int id = tid + 256 * i;
        int r = id >> 6, c = id & 63;
        float4 v = e4[r * (EMB_STRIDE / 4) + c];
        v.x = tf32r(v.x); v.y = tf32r(v.y); v.z = tf32r(v.z); v.w = tf32r(v.w);
        e4[r * (EMB_STRIDE / 4) + c] = v;
    }
    float4* w4 = reinterpret_cast<float4*>(WS);
    #pragma unroll
    for (int i = 0; i < 16; ++i) {
        int id = tid + 256 * i;
        int k = id >> 4, c = id & 15;
        float4 v = w4[k * (W_STRIDE / 4) + c];
        v.x = tf32r(v.x); v.y = tf32r(v.y); v.z = tf32r(v.z); v.w = tf32r(v.w);
        w4[k * (W_STRIDE / 4) + c] = v;
    }
    __syncthreads();

    // ---- mma: warp w -> rows [16w, 16w+16), all 64 cols, K=256 ----
    const int wi = tid >> 5, lane = tid & 31;
    const int gid = lane >> 2, tig = lane & 3;

    float sacc[8][4];
    #pragma unroll
    for (int nt = 0; nt < 8; ++nt)
        #pragma unroll
        for (int q = 0; q < 4; ++q) sacc[nt][q] = 0.0f;

    const float* arow = embS + (16 * wi + gid) * EMB_STRIDE + tig;
    #pragma unroll 4
    for (int j = 0; j < 32; ++j) {
        uint32_t a0 = __float_as_uint(arow[8 * j]);
        uint32_t a1 = __float_as_uint(arow[8 * EMB_STRIDE + 8 * j]);
        uint32_t a2 = __float_as_uint(arow[8 * j + 4]);
        uint32_t a3 = __float_as_uint(arow[8 * EMB_STRIDE + 8 * j + 4]);
        const float* brow = WS + (8 * j + tig) * W_STRIDE + gid;
        #pragma unroll
        for (int nt = 0; nt < 8; ++nt) {
            uint32_t b0 = __float_as_uint(brow[8 * nt]);
            uint32_t b1 = __float_as_uint(brow[4 * W_STRIDE + 8 * nt]);
            mma_tf32(sacc[nt][0], sacc[nt][1], sacc[nt][2], sacc[nt][3],
                     a0, a1, a2, a3, b0, b1);
        }
    }

    // ---- epilogue: scale + tf32-round, coalesced float2 stores ----
    const int rbase = bx * 128 + 16 * wi;
    #pragma unroll
    for (int nt = 0; nt < 8; ++nt) {
        int c = 8 * nt + 2 * tig;
        *reinterpret_cast<float2*>(&outp[(size_t)(rbase + gid) * H_ + c]) =
            make_float2(tf32r(sacc[nt][0] * scale), tf32r(sacc[nt][1] * scale));
        *reinterpret_cast<float2*>(&outp[(size_t)(rbase + gid + 8) * H_ + c]) =
            make_float2(tf32r(sacc[nt][2] * scale), tf32r(sacc[nt][3] * scale));
    }
}

// ============================================================
// Warp-MMA tf32 flash attention (R15 config: 128 thr, 4 warps,
// warp = 32 rows x 32 kc). V tiles row-major (stride 72).
// ============================================================
#define K_STRIDE 68
#define V_STRIDE 72
#define KT_F (64 * K_STRIDE)     // 4352
#define VT_F (64 * V_STRIDE)     // 4608
#define OFF_K0 0
#define OFF_K1 KT_F
#define OFF_V0 (2 * KT_F)
#define OFF_V1 (2 * KT_F + VT_F)
#define FLASH_SMEM ((2 * KT_F + 2 * VT_F) * 4)   // 71,680 B

#define OSH_STRIDE 66

// async-copy one 64x64 f32 tile (gmem row-major, ld=64) into padded smem
__device__ __forceinline__ void cp_tile(uint32_t smf_byte, const float* src, int tid,
                                        int strideF) {
    #pragma unroll
    for (int i = 0; i < 8; ++i) {
        int id = tid + 128 * i;
        int r = id >> 4;
        int c16 = id & 15;
        cp16(smf_byte + (uint32_t)(r * strideF + c16 * 4) * 4u,
             src + (size_t)r * 64 + c16 * 4);
    }
}

__global__ __launch_bounds__(128, 2) void flash_kernel(float* __restrict__ out) {
    extern __shared__ float fs[];
    const uint32_t smb = smem_u32(fs);
    const int tid = threadIdx.x;
    const int w = tid >> 5, lane = tid & 31;
    const int rg = w >> 1, kg = w & 1;
    const int gid = lane >> 2, tig = lane & 3;
    const int b = blockIdx.y, qblk = blockIdx.x;

    const float* kgb = g_k + (size_t)b * S_ * H_;
    const float* vgb = g_v + (size_t)b * S_ * H_;

    // preload tile 0 first so cp.async overlaps the Q LDGs
    cp_tile(smb + OFF_K0 * 4, kgb, tid, K_STRIDE);
    cp_tile(smb + OFF_V0 * 4, vgb, tid, V_STRIDE);
    cp_commit();

    // ---- Q A-fragments: warp covers rows [32rg, 32rg+32) ----
    uint32_t qa[2][8][4];
    {
        const float* q0 = g_q + ((size_t)b * S_ + (size_t)qblk * 64 + 32 * rg) * H_;
        #pragma unroll
        for (int rb = 0; rb < 2; ++rb)
            #pragma unroll
            for (int j = 0; j < 8; ++j) {
                const float* qr = q0 + (size_t)(16 * rb + gid) * H_ + 8 * j + tig;
                qa[rb][j][0] = __float_as_uint(qr[0]);
                qa[rb][j][1] = __float_as_uint(qr[8 * H_]);
                qa[rb][j][2] = __float_as_uint(qr[4]);
                qa[rb][j][3] = __float_as_uint(qr[8 * H_ + 4]);
            }
    }

    float oacc[2][8][4];
    #pragma unroll
    for (int rb = 0; rb < 2; ++rb)
        #pragma unroll
        for (int ht = 0; ht < 8; ++ht)
            #pragma unroll
            for (int q = 0; q < 4; ++q) oacc[rb][ht][q] = 0.0f;
    float lsum[2][2] = { {0.0f, 0.0f}, {0.0f, 0.0f} };

    const int srcA = (lane & ~3) | (tig >> 1);
    const int srcB = srcA + 2;
    const bool oddt = (tig & 1);

    for (int kt = 0; kt < 64; ++kt) {
        const int cur = kt & 1;
        if (kt < 63) {
            const int nf = (cur ^ 1) ? OFF_K1 : OFF_K0;
            const int nv = (cur ^ 1) ? OFF_V1 : OFF_V0;
            cp_tile(smb + nf * 4, kgb + (size_t)(kt + 1) * 64 * H_, tid, K_STRIDE);
            cp_tile(smb + nv * 4, vgb + (size_t)(kt + 1) * 64 * H_, tid, V_STRIDE);
            cp_commit();
            cp_wait1();
        } else {
            cp_wait0();
        }
        __syncthreads();

        const float* Ks = fs + (cur ? OFF_K1 : OFF_K0);
        const float* Vs = fs + (cur ? OFF_V1 : OFF_V0);

        // ---- S = Q K^T over this warp's 32 kv cols ----
        float p[2][4][4];
        #pragma unroll
        for (int rb = 0; rb < 2; ++rb)
            #pragma unroll
            for (int nt = 0; nt < 4; ++nt)
                #pragma unroll
                for (int q = 0; q < 4; ++q) p[rb][nt][q] = 0.0f;

        #pragma unroll
        for (int j = 0; j < 8; ++j) {
            #pragma unroll
            for (int nt = 0; nt < 4; ++nt) {
                const float* kr = Ks + (32 * kg + 8 * nt + gid) * K_STRIDE + 8 * j + tig;
                uint32_t kb0 = __float_as_uint(kr[0]);
                uint32_t kb1 = __float_as_uint(kr[4]);
                mma_tf32(p[0][nt][0], p[0][nt][1], p[0][nt][2], p[0][nt][3],
                         qa[0][j][0], qa[0][j][1], qa[0][j][2], qa[0][j][3], kb0, kb1);
                mma_tf32(p[1][nt][0], p[1][nt][1], p[1][nt][2], p[1][nt][3],
                         qa[1][j][0], qa[1][j][1], qa[1][j][2], qa[1][j][3], kb0, kb1);
            }
        }

        // ---- P = 2^S (log2 domain), tf32-rounded; partial l ----
        #pragma unroll
        for (int rb = 0; rb < 2; ++rb)
            #pragma unroll
            for (int nt = 0; nt < 4; ++nt) {
                float p0 = exp2_fast(p[rb][nt][0]);
                float p1 = exp2_fast(p[rb][nt][1]);
                float p2 = exp2_fast(p[rb][nt][2]);
                float p3 = exp2_fast(p[rb][nt][3]);
                lsum[rb][0] += p0 + p1;
                lsum[rb][1] += p2 + p3;
                p[rb][nt][0] = tf32r(p0);
                p[rb][nt][1] = tf32r(p1);
                p[rb][nt][2] = tf32r(p2);
                p[rb][nt][3] = tf32r(p3);
            }

        // ---- O += P V over this warp's 32 kc (A-frags via quad shuffle) ----
        #pragma unroll
        for (int kb = 0; kb < 4; ++kb) {
            uint32_t A[2][4];
            #pragma unroll
            for (int rb = 0; rb < 2; ++rb) {
                float x0 = __shfl_sync(0xffffffffu, p[rb][kb][0], srcA);
                float x1 = __shfl_sync(0xffffffffu, p[rb][kb][1], srcA);
                float y0 = __shfl_sync(0xffffffffu, p[rb][kb][2], srcA);
                float y1 = __shfl_sync(0xffffffffu, p[rb][kb][3], srcA);
                float z0 = __shfl_sync(0xffffffffu, p[rb][kb][0], srcB);
                float z1 = __shfl_sync(0xffffffffu, p[rb][kb][1], srcB);
                float u0 = __shfl_sync(0xffffffffu, p[rb][kb][2], srcB);
                float u1 = __shfl_sync(0xffffffffu, p[rb][kb][3], srcB);
                A[rb][0] = __float_as_uint(oddt ? x1 : x0);
                A[rb][1] = __float_as_uint(oddt ? y1 : y0);
                A[rb][2] = __float_as_uint(oddt ? z1 : z0);
                A[rb][3] = __float_as_uint(oddt ? u1 : u0);
            }
            #pragma unroll
            for (int ht = 0; ht < 8; ++ht) {
                // row-major V tile: B[k=kc][n=h]
                const float* vr = Vs + (32 * kg + 8 * kb + tig) * V_STRIDE + 8 * ht + gid;
                uint32_t vb0 = __float_as_uint(vr[0]);
                uint32_t vb1 = __float_as_uint(vr[4 * V_STRIDE]);
                mma_tf32(oacc[0][ht][0], oacc[0][ht][1], oacc[0][ht][2], oacc[0][ht][3],
                         A[0][0], A[0][1], A[0][2], A[0][3], vb0, vb1);
                mma_tf32(oacc[1][ht][0], oacc[1][ht][1], oacc[1][ht][2], oacc[1][ht][3],
                         A[1][0], A[1][1], A[1][2], A[1][3], vb0, vb1);
            }
        }
        __syncthreads();
    }

    // ---- epilogue: quad-reduce l, combine kc-halves through smem ----
    #pragma unroll
    for (int rb = 0; rb < 2; ++rb)
        #pragma unroll
        for (int r = 0; r < 2; ++r) {
            lsum[rb][r] += __shfl_xor_sync(0xffffffffu, lsum[rb][r], 1);
            lsum[rb][r] += __shfl_xor_sync(0xffffffffu, lsum[rb][r], 2);
        }

    float* Osh = fs + OFF_K0;             // [64][OSH_STRIDE] (fits in K0 region)
    float* Lsh = fs + OFF_V0;             // [64]
    if (kg == 1) {
        #pragma unroll
        for (int rb = 0; rb < 2; ++rb) {
            int row0 = 32 * rg + 16 * rb + gid;
            if (tig == 0) { Lsh[row0] = lsum[rb][0]; Lsh[row0 + 8] = lsum[rb][1]; }
            #pragma unroll
            for (int ht = 0; ht < 8; ++ht) {
                int c = 8 * ht + 2 * tig;
                *reinterpret_cast<float2*>(&Osh[row0 * OSH_STRIDE + c]) =
                    make_float2(oacc[rb][ht][0], oacc[rb][ht][1]);
                *reinterpret_cast<float2*>(&Osh[(row0 + 8) * OSH_STRIDE + c]) =
                    make_float2(oacc[rb][ht][2], oacc[rb][ht][3]);
            }
        }
    }
    __syncthreads();
    if (kg == 0) {
        float* ob = out + ((size_t)b * S_ + (size_t)qblk * 64) * H_;
        #pragma unroll
        for (int rb = 0; rb < 2; ++rb) {
            int row0 = 32 * rg + 16 * rb + gid;
            int row1 = row0 + 8;
            float inv0 = 1.0f / (lsum[rb][0] + Lsh[row0]);
            float inv1 = 1.0f / (lsum[rb][1] + Lsh[row1]);
            #pragma unroll
            for (int ht = 0; ht < 8; ++ht) {
                int c = 8 * ht + 2 * tig;
                float2 q0 = *reinterpret_cast<const float2*>(&Osh[row0 * OSH_STRIDE + c]);
                float2 q1 = *reinterpret_cast<const float2*>(&Osh[row1 * OSH_STRIDE + c]);
                *reinterpret_cast<float2*>(&ob[(size_t)row0 * H_ + c]) =
                    make_float2((oacc[rb][ht][0] + q0.x) * inv0,
                                (oacc[rb][ht][1] + q0.y) * inv0);
                *reinterpret_cast<float2*>(&ob[(size_t)row1 * H_ + c]) =
                    make_float2((oacc[rb][ht][2] + q1.x) * inv1,
                                (oacc[rb][ht][3] + q1.y) * inv1);
            }
        }
    }
}

// ============================================================
// launch
// ============================================================
extern "C" void kernel_launch(void* const* d_in, const int* in_sizes, int n_in,
                              void* d_out, int out_size) {
    const float* emb = (const float*)d_in[0];
    const float* wk  = (const float*)d_in[1];
    const float* wq  = (const float*)d_in[2];
    const float* wv  = (const float*)d_in[3];
    float* out = (float*)d_out;

    cudaFuncSetAttribute(proj_kernel,  cudaFuncAttributeMaxDynamicSharedMemorySize, PROJ_SMEM);
    cudaFuncSetAttribute(flash_kernel, cudaFuncAttributeMaxDynamicSharedMemorySize, FLASH_SMEM);

    dim3 pgrid(B_ * S_ / 128, 3);
    proj_kernel<<<pgrid, 256, PROJ_SMEM>>>(emb, wq, wk, wv);

    dim3 fgrid(S_ / 64, B_);
    flash_kernel<<<fgrid, 128, FLASH_SMEM>>>(out);
}